// round 7
// baseline (speedup 1.0000x reference)
#include <cuda_runtime.h>
#include <cstdint>

// Problem dims (fixed by the dataset)
#define O_DIM   4096
#define I_DIM   2048
#define K_ACT   2048
#define N_TOK   4096
#define M_DENSE 8192

// Scratch (device globals; allocation-free rule)
// NOTE: columns are stored PERMUTED within each 8-group: physical p holds
// logical (p>>1) + (p&1)*4, i.e. logical order [0,4,1,5,2,6,3,7].
// This makes mma fragment halves (c, c+4) adjacent -> ld.shared.v2.
__device__ float g_Wg[(size_t)O_DIM * K_ACT];   // gathered weight, tf32, permuted
__device__ float g_Bc[(size_t)N_TOK * K_ACT];   // activations, tf32, permuted

__device__ __forceinline__ uint32_t tf32_rna(float f) {
    uint32_t u;
    asm("cvt.rna.tf32.f32 %0, %1;" : "=r"(u) : "f"(f));
    return u;
}
__device__ __forceinline__ uint32_t f2u(float f) { return __float_as_uint(f); }

// ===========================================================================
// Kernel 1: gather compressed weight -> Wg[o][jp] (physical col), tf32
// ===========================================================================
__global__ void build_wg_kernel(const float* __restrict__ weight,
                                const int*   __restrict__ idx,
                                const int*   __restrict__ metadata) {
    int t = blockIdx.x * blockDim.x + threadIdx.x;   // physical (o, p)
    int p = t & (K_ACT - 1);
    int o = t >> 11;
    // logical column from physical (un-permute within 8-group)
    int j = (p & ~7) | (((p >> 1) & 3) + ((p & 1) << 2));
    int kd = __ldg(idx + j);
    int g  = kd >> 2;
    int q  = kd & 3;
    const int2 md = *reinterpret_cast<const int2*>(metadata + (size_t)o * I_DIM + 2 * g);
    float v = 0.0f;
    if (md.x == q)      v = __ldg(weight + (size_t)o * I_DIM + 2 * g);
    else if (md.y == q) v = __ldg(weight + (size_t)o * I_DIM + 2 * g + 1);
    reinterpret_cast<uint32_t*>(g_Wg)[t] = tf32_rna(v);
}

// ===========================================================================
// Kernel 2: tf32-round + permute activations (8 logical floats per thread)
//   physical: {l0,l4,l1,l5, l2,l6,l3,l7}
// ===========================================================================
__global__ void convert_b_kernel(const float4* __restrict__ input) {
    int t = blockIdx.x * blockDim.x + threadIdx.x;   // one 8-group
    float4 f0 = input[t * 2];
    float4 f1 = input[t * 2 + 1];
    uint4 lo, hi;
    lo.x = tf32_rna(f0.x); lo.y = tf32_rna(f1.x);
    lo.z = tf32_rna(f0.y); lo.w = tf32_rna(f1.y);
    hi.x = tf32_rna(f0.z); hi.y = tf32_rna(f1.z);
    hi.z = tf32_rna(f0.w); hi.w = tf32_rna(f1.w);
    uint4* dst = reinterpret_cast<uint4*>(g_Bc) + t * 2;
    dst[0] = lo;
    dst[1] = hi;
}

// ===========================================================================
// Kernel 3: zero-fill output
// ===========================================================================
__global__ void zero_out_kernel(float4* __restrict__ out) {
    size_t t = (size_t)blockIdx.x * blockDim.x + threadIdx.x;
    out[t] = make_float4(0.f, 0.f, 0.f, 0.f);
}

// ===========================================================================
// Kernel 4: tf32 mma.sync GEMM with row-scatter epilogue
//   CTA: 128x128, KC=32, 256 thr = 8 warps (4m x 2n), warp tile 32x64.
//   2-stage cp.async double buffer + fragment double-buffer over ks.
// ===========================================================================
#define MT      128
#define NT      128
#define KC      32
#define KITERS  (K_ACT / KC)          // 64
#define LDSTR   36                    // padded floats per smem row (144B)
#define A_FLTS  (MT * LDSTR)
#define B_FLTS  (NT * LDSTR)
#define STG_FLTS (A_FLTS + B_FLTS)    // 9216 floats
#define SMEM_DYN (2 * STG_FLTS * 4)   // 73728 B

__device__ __forceinline__ void mma_tf32(float* c,
    uint32_t a0, uint32_t a1, uint32_t a2, uint32_t a3,
    uint32_t b0, uint32_t b1) {
    asm volatile(
        "mma.sync.aligned.m16n8k8.row.col.f32.tf32.tf32.f32 "
        "{%0,%1,%2,%3}, {%4,%5,%6,%7}, {%8,%9}, {%0,%1,%2,%3};"
        : "+f"(c[0]), "+f"(c[1]), "+f"(c[2]), "+f"(c[3])
        : "r"(a0), "r"(a1), "r"(a2), "r"(a3), "r"(b0), "r"(b1));
}
__device__ __forceinline__ void cp_async16(void* dst_smem, const void* src) {
    uint32_t d;
    asm("{ .reg .u64 t; cvta.to.shared.u64 t, %1; cvt.u32.u64 %0, t; }"
        : "=r"(d) : "l"(dst_smem));
    asm volatile("cp.async.cg.shared.global [%0], [%1], 16;" :: "r"(d), "l"(src));
}

__global__ __launch_bounds__(256, 2)
void gemm_mma_kernel(const int* __restrict__ indices,
                     float*     __restrict__ out) {
    extern __shared__ float smem[];
    const float* Ag = g_Wg;
    const float* Bg = g_Bc;

    const int tid  = threadIdx.x;
    const int lane = tid & 31;
    const int wid  = tid >> 5;
    const int wm   = wid >> 1;        // 0..3 -> m offset wm*32
    const int wn   = wid & 1;         // 0..1 -> n offset wn*64
    const int bm   = blockIdx.y * MT;
    const int bn   = blockIdx.x * NT;

    float acc[2][8][4];
#pragma unroll
    for (int mi = 0; mi < 2; mi++)
#pragma unroll
        for (int ni = 0; ni < 8; ni++)
#pragma unroll
            for (int q = 0; q < 4; q++) acc[mi][ni][q] = 0.0f;

    auto load_stage = [&](int kc, int s) {
        float* As = smem + s * STG_FLTS;
        float* Bs = As + A_FLTS;
#pragma unroll
        for (int i = 0; i < 4; i++) {               // A: 1024 float4
            int f = i * 256 + tid;
            int row = f >> 3, c4 = (f & 7) << 2;
            cp_async16(As + row * LDSTR + c4,
                       Ag + (size_t)(bm + row) * K_ACT + kc * KC + c4);
        }
#pragma unroll
        for (int i = 0; i < 4; i++) {               // B: 1024 float4
            int f = i * 256 + tid;
            int row = f >> 3, c4 = (f & 7) << 2;
            cp_async16(Bs + row * LDSTR + c4,
                       Bg + (size_t)(bn + row) * K_ACT + kc * KC + c4);
        }
    };

    // per-thread fragment base offsets (physical 2q column within 8-group)
    const int q2 = 2 * (lane & 3);
    const int ar = wm * 32 + (lane >> 2);
    const int br = wn * 64 + (lane >> 2);

    load_stage(0, 0);
    asm volatile("cp.async.commit_group;" ::: "memory");

    for (int kc = 0; kc < KITERS; kc++) {
        if (kc + 1 < KITERS) load_stage(kc + 1, (kc + 1) & 1);
        asm volatile("cp.async.commit_group;" ::: "memory");
        asm volatile("cp.async.wait_group 1;" ::: "memory");
        __syncthreads();

        const float* As = smem + (kc & 1) * STG_FLTS;
        const float* Bs = As + A_FLTS;
        const float* pa = As + ar * LDSTR + q2;   // + mi*16*LDSTR (+8*LDSTR)
        const float* pb = Bs + br * LDSTR + q2;   // + ni*8*LDSTR

        float2 af[2][2][2];   // [buf][mi][half]
        float2 bf[2][8];      // [buf][ni]

        // prologue: fragments for ks = 0
#pragma unroll
        for (int mi = 0; mi < 2; mi++) {
            af[0][mi][0] = *reinterpret_cast<const float2*>(pa + mi * 16 * LDSTR);
            af[0][mi][1] = *reinterpret_cast<const float2*>(pa + (mi * 16 + 8) * LDSTR);
        }
#pragma unroll
        for (int ni = 0; ni < 8; ni++)
            bf[0][ni] = *reinterpret_cast<const float2*>(pb + ni * 8 * LDSTR);

#pragma unroll
        for (int ks = 0; ks < 4; ks++) {
            const int cur = ks & 1, nxt = cur ^ 1;
            if (ks < 3) {
                const int c8 = (ks + 1) * 8;
#pragma unroll
                for (int mi = 0; mi < 2; mi++) {
                    af[nxt][mi][0] = *reinterpret_cast<const float2*>(
                        pa + mi * 16 * LDSTR + c8);
                    af[nxt][mi][1] = *reinterpret_cast<const float2*>(
                        pa + (mi * 16 + 8) * LDSTR + c8);
                }
#pragma unroll
                for (int ni = 0; ni < 8; ni++)
                    bf[nxt][ni] = *reinterpret_cast<const float2*>(
                        pb + ni * 8 * LDSTR + c8);
            }
#pragma unroll
            for (int mi = 0; mi < 2; mi++)
#pragma unroll
                for (int ni = 0; ni < 8; ni++)
                    mma_tf32(acc[mi][ni],
                             f2u(af[cur][mi][0].x), f2u(af[cur][mi][1].x),
                             f2u(af[cur][mi][0].y), f2u(af[cur][mi][1].y),
                             f2u(bf[cur][ni].x),    f2u(bf[cur][ni].y));
        }
        __syncthreads();
    }

    // ---- epilogue: scatter rows via indices ----
#pragma unroll
    for (int mi = 0; mi < 2; mi++) {
        int r0 = bm + wm * 32 + mi * 16 + (lane >> 2);
        int o0 = __ldg(indices + r0);
        int o1 = __ldg(indices + r0 + 8);
        float* d0 = out + (size_t)o0 * N_TOK + bn + wn * 64 + 2 * (lane & 3);
        float* d1 = out + (size_t)o1 * N_TOK + bn + wn * 64 + 2 * (lane & 3);
#pragma unroll
        for (int ni = 0; ni < 8; ni++) {
            float2 v0 = make_float2(acc[mi][ni][0], acc[mi][ni][1]);
            float2 v1 = make_float2(acc[mi][ni][2], acc[mi][ni][3]);
            *reinterpret_cast<float2*>(d0 + ni * 8) = v0;
            *reinterpret_cast<float2*>(d1 + ni * 8) = v1;
        }
    }
}

// ===========================================================================
// Host launcher
// ===========================================================================
extern "C" void kernel_launch(void* const* d_in, const int* in_sizes, int n_in,
                              void* d_out, int out_size) {
    const float* input    = (const float*)d_in[0];
    const int*   idx      = (const int*)  d_in[1];
    const float* weight   = (const float*)d_in[2];
    const int*   indices  = (const int*)  d_in[3];
    const int*   metadata = (const int*)  d_in[4];
    if (in_sizes[1] == O_DIM && in_sizes[3] == K_ACT) {
        const int* t = idx; idx = indices; indices = t;
    }
    float* out = (float*)d_out;

    cudaFuncSetAttribute(gemm_mma_kernel,
                         cudaFuncAttributeMaxDynamicSharedMemorySize, SMEM_DYN);

    // 1) gather + tf32-round weight (permuted cols)
    build_wg_kernel<<<(O_DIM * K_ACT) / 256, 256>>>(weight, idx, metadata);
    // 2) tf32-round + permute activations
    convert_b_kernel<<<(N_TOK * K_ACT / 8) / 256, 256>>>((const float4*)input);
    // 3) zero dense output
    zero_out_kernel<<<(M_DENSE * N_TOK / 4) / 256, 256>>>((float4*)out);
    // 4) tensor-core GEMM + scatter
    dim3 grid(N_TOK / NT, O_DIM / MT);   // 32 x 32
    gemm_mma_kernel<<<grid, 256, SMEM_DYN>>>(indices, out);
}

// round 8
// speedup vs baseline: 2.2695x; 2.2695x over previous
#include <cuda_runtime.h>
#include <cuda_fp16.h>
#include <cstdint>

// Problem dims (fixed by the dataset)
#define O_DIM   4096
#define I_DIM   2048
#define K_ACT   2048
#define N_TOK   4096
#define M_DENSE 8192

// Scratch (device globals; allocation-free rule): fp16 operands
__device__ __half g_Wh[(size_t)O_DIM * K_ACT];   // gathered weight, fp16
__device__ __half g_Bh[(size_t)N_TOK * K_ACT];   // activations, fp16

// ===========================================================================
// Kernel 1: gather compressed weight -> Wh[o][j], fp16
// ===========================================================================
__global__ void build_wg_kernel(const float* __restrict__ weight,
                                const int*   __restrict__ idx,
                                const int*   __restrict__ metadata) {
    int t = blockIdx.x * blockDim.x + threadIdx.x;
    int j = t & (K_ACT - 1);
    int o = t >> 11;
    int kd = __ldg(idx + j);
    int g  = kd >> 2;
    int p  = kd & 3;
    const int2 md = *reinterpret_cast<const int2*>(metadata + (size_t)o * I_DIM + 2 * g);
    float v = 0.0f;
    if (md.x == p)      v = __ldg(weight + (size_t)o * I_DIM + 2 * g);
    else if (md.y == p) v = __ldg(weight + (size_t)o * I_DIM + 2 * g + 1);
    g_Wh[t] = __float2half_rn(v);
}

// ===========================================================================
// Kernel 2: fp16-convert activations (8 floats -> 8 halves per thread)
// ===========================================================================
__global__ void convert_b_kernel(const float4* __restrict__ input) {
    int t = blockIdx.x * blockDim.x + threadIdx.x;
    float4 f0 = input[t * 2];
    float4 f1 = input[t * 2 + 1];
    __half2 h[4];
    h[0] = __floats2half2_rn(f0.x, f0.y);
    h[1] = __floats2half2_rn(f0.z, f0.w);
    h[2] = __floats2half2_rn(f1.x, f1.y);
    h[3] = __floats2half2_rn(f1.z, f1.w);
    *(reinterpret_cast<uint4*>(g_Bh) + t) = *reinterpret_cast<uint4*>(h);
}

// ===========================================================================
// Kernel 3: zero-fill output
// ===========================================================================
__global__ void zero_out_kernel(float4* __restrict__ out) {
    size_t t = (size_t)blockIdx.x * blockDim.x + threadIdx.x;
    out[t] = make_float4(0.f, 0.f, 0.f, 0.f);
}

// ===========================================================================
// Kernel 4: fp16 mma.sync m16n8k16 GEMM with row-scatter epilogue
//   C[o, n] = sum_j Wh[o, j] * Bh[n, j]  -> out[indices[o], n]
//   CTA 128x128, KC=64 halves, 256 thr = 8 warps (4m x 2n), warp tile 32x64.
//   2-stage cp.async double buffer; fragments via ldmatrix.x4.
// ===========================================================================
#define MT      128
#define NT      128
#define KC      64
#define KITERS  (K_ACT / KC)          // 32
#define STRH    72                    // halves per smem row (144 B; banks 4r+q)
#define ROWB    (STRH * 2)            // 144 bytes
#define A_BYTES (MT * ROWB)           // 18432
#define B_BYTES (NT * ROWB)           // 18432
#define STG_BYTES (A_BYTES + B_BYTES) // 36864
#define SMEM_DYN (2 * STG_BYTES)      // 73728 B -> 2 CTAs/SM

__device__ __forceinline__ uint32_t smem_u32(const void* p) {
    uint32_t a;
    asm("{ .reg .u64 t; cvta.to.shared.u64 t, %1; cvt.u32.u64 %0, t; }"
        : "=r"(a) : "l"(p));
    return a;
}
__device__ __forceinline__ void ldsm_x4(uint32_t* r, uint32_t addr) {
    asm volatile("ldmatrix.sync.aligned.m8n8.x4.shared.b16 {%0,%1,%2,%3}, [%4];"
                 : "=r"(r[0]), "=r"(r[1]), "=r"(r[2]), "=r"(r[3]) : "r"(addr));
}
__device__ __forceinline__ void mma_f16(float* c, const uint32_t* a,
                                        uint32_t b0, uint32_t b1) {
    asm volatile(
        "mma.sync.aligned.m16n8k16.row.col.f32.f16.f16.f32 "
        "{%0,%1,%2,%3}, {%4,%5,%6,%7}, {%8,%9}, {%0,%1,%2,%3};"
        : "+f"(c[0]), "+f"(c[1]), "+f"(c[2]), "+f"(c[3])
        : "r"(a[0]), "r"(a[1]), "r"(a[2]), "r"(a[3]), "r"(b0), "r"(b1));
}
__device__ __forceinline__ void cp_async16(void* dst_smem, const void* src) {
    uint32_t d;
    asm("{ .reg .u64 t; cvta.to.shared.u64 t, %1; cvt.u32.u64 %0, t; }"
        : "=r"(d) : "l"(dst_smem));
    asm volatile("cp.async.cg.shared.global [%0], [%1], 16;" :: "r"(d), "l"(src));
}

__global__ __launch_bounds__(256, 2)
void gemm_mma_kernel(const int* __restrict__ indices,
                     float*     __restrict__ out) {
    extern __shared__ char smem[];
    const __half* Ag = g_Wh;
    const __half* Bg = g_Bh;

    const int tid  = threadIdx.x;
    const int lane = tid & 31;
    const int wid  = tid >> 5;
    const int wm   = wid >> 1;        // 0..3 -> m offset wm*32
    const int wn   = wid & 1;         // 0..1 -> n offset wn*64
    const int bm   = blockIdx.y * MT;
    const int bn   = blockIdx.x * NT;

    float acc[2][8][4];
#pragma unroll
    for (int mi = 0; mi < 2; mi++)
#pragma unroll
        for (int ni = 0; ni < 8; ni++)
#pragma unroll
            for (int q = 0; q < 4; q++) acc[mi][ni][q] = 0.0f;

    // cp.async stage loader: A 128x64h, B 128x64h; 8 halves (16B) per op
    auto load_stage = [&](int kc, int s) {
        char* As = smem + s * STG_BYTES;
        char* Bs = As + A_BYTES;
#pragma unroll
        for (int i = 0; i < 4; i++) {               // A: 1024 ops
            int f = i * 256 + tid;
            int row = f >> 3, c = (f & 7) << 3;     // halves
            cp_async16(As + row * ROWB + c * 2,
                       Ag + (size_t)(bm + row) * K_ACT + kc * KC + c);
        }
#pragma unroll
        for (int i = 0; i < 4; i++) {               // B: 1024 ops
            int f = i * 256 + tid;
            int row = f >> 3, c = (f & 7) << 3;
            cp_async16(Bs + row * ROWB + c * 2,
                       Bg + (size_t)(bn + row) * K_ACT + kc * KC + c);
        }
    };

    // ldmatrix per-lane row addressing (byte offsets)
    const uint32_t smem_b = smem_u32(smem);
    // A x4: mats (r0-7,k0-7)(r8-15,k0-7)(r0-7,k8-15)(r8-15,k8-15)
    const int a_row  = wm * 32 + (lane & 7) + (lane & 8);
    const int a_koff = (lane >> 4) << 3;            // halves
    // B x4: mats (n0-7,k0-7)(n0-7,k8-15)(n8-15,k0-7)(n8-15,k8-15)
    const int b_row  = wn * 64 + (lane & 7) + ((lane >> 4) << 3);
    const int b_koff = (lane & 8);                  // halves

    load_stage(0, 0);
    asm volatile("cp.async.commit_group;" ::: "memory");

    for (int kc = 0; kc < KITERS; kc++) {
        if (kc + 1 < KITERS) load_stage(kc + 1, (kc + 1) & 1);
        asm volatile("cp.async.commit_group;" ::: "memory");
        asm volatile("cp.async.wait_group 1;" ::: "memory");
        __syncthreads();

        const uint32_t As = smem_b + (kc & 1) * STG_BYTES;
        const uint32_t Bs = As + A_BYTES;
        const uint32_t aAddr = As + a_row * ROWB + a_koff * 2;
        const uint32_t bAddr = Bs + b_row * ROWB + b_koff * 2;

#pragma unroll
        for (int ks = 0; ks < 4; ks++) {
            const int k0b = ks * 32;                // k16 * 2 bytes
            uint32_t aa[2][4];
#pragma unroll
            for (int mi = 0; mi < 2; mi++)
                ldsm_x4(aa[mi], aAddr + mi * 16 * ROWB + k0b);
            uint32_t bb[4][4];
#pragma unroll
            for (int pr = 0; pr < 4; pr++)
                ldsm_x4(bb[pr], bAddr + pr * 16 * ROWB + k0b);
#pragma unroll
            for (int mi = 0; mi < 2; mi++)
#pragma unroll
                for (int ni = 0; ni < 8; ni++)
                    mma_f16(acc[mi][ni], aa[mi],
                            bb[ni >> 1][(ni & 1) * 2],
                            bb[ni >> 1][(ni & 1) * 2 + 1]);
        }
        __syncthreads();
    }

    // ---- epilogue: scatter rows via indices ----
#pragma unroll
    for (int mi = 0; mi < 2; mi++) {
        int r0 = bm + wm * 32 + mi * 16 + (lane >> 2);
        int o0 = __ldg(indices + r0);
        int o1 = __ldg(indices + r0 + 8);
        float* d0 = out + (size_t)o0 * N_TOK + bn + wn * 64 + 2 * (lane & 3);
        float* d1 = out + (size_t)o1 * N_TOK + bn + wn * 64 + 2 * (lane & 3);
#pragma unroll
        for (int ni = 0; ni < 8; ni++) {
            float2 v0 = make_float2(acc[mi][ni][0], acc[mi][ni][1]);
            float2 v1 = make_float2(acc[mi][ni][2], acc[mi][ni][3]);
            *reinterpret_cast<float2*>(d0 + ni * 8) = v0;
            *reinterpret_cast<float2*>(d1 + ni * 8) = v1;
        }
    }
}

// ===========================================================================
// Host launcher
// ===========================================================================
extern "C" void kernel_launch(void* const* d_in, const int* in_sizes, int n_in,
                              void* d_out, int out_size) {
    const float* input    = (const float*)d_in[0];
    const int*   idx      = (const int*)  d_in[1];
    const float* weight   = (const float*)d_in[2];
    const int*   indices  = (const int*)  d_in[3];
    const int*   metadata = (const int*)  d_in[4];
    if (in_sizes[1] == O_DIM && in_sizes[3] == K_ACT) {
        const int* t = idx; idx = indices; indices = t;
    }
    float* out = (float*)d_out;

    cudaFuncSetAttribute(gemm_mma_kernel,
                         cudaFuncAttributeMaxDynamicSharedMemorySize, SMEM_DYN);

    // 1) gather + fp16-convert weight
    build_wg_kernel<<<(O_DIM * K_ACT) / 256, 256>>>(weight, idx, metadata);
    // 2) fp16-convert activations
    convert_b_kernel<<<(N_TOK * K_ACT / 8) / 256, 256>>>((const float4*)input);
    // 3) zero dense output
    zero_out_kernel<<<(M_DENSE * N_TOK / 4) / 256, 256>>>((float4*)out);
    // 4) tensor-core GEMM + scatter
    dim3 grid(N_TOK / NT, O_DIM / MT);   // 32 x 32
    gemm_mma_kernel<<<grid, 256, SMEM_DYN>>>(indices, out);
}

// round 9
// speedup vs baseline: 2.4331x; 1.0721x over previous
#include <cuda_runtime.h>
#include <cuda_fp16.h>
#include <cstdint>

// Problem dims (fixed by the dataset)
#define O_DIM   4096
#define I_DIM   2048
#define K_ACT   2048
#define N_TOK   4096
#define M_DENSE 8192

// Scratch (device globals; allocation-free rule): fp16 operands
__device__ __half g_Wh[(size_t)O_DIM * K_ACT];   // gathered weight, fp16
__device__ __half g_Bh[(size_t)N_TOK * K_ACT];   // activations, fp16

// ===========================================================================
// Kernel 1: gather compressed weight -> Wh[o][j], fp16. 4 elems/thread (MLP).
// ===========================================================================
__global__ void build_wg_kernel(const float* __restrict__ weight,
                                const int*   __restrict__ idx,
                                const int*   __restrict__ metadata) {
    int t  = blockIdx.x * blockDim.x + threadIdx.x;   // group of 4 (o, j)
    int o  = t >> 9;                                   // 512 groups per o
    int j0 = (t & 511) << 2;
    const int4 kd4 = *reinterpret_cast<const int4*>(idx + j0);
    const int* md_row = metadata + (size_t)o * I_DIM;
    const float* w_row = weight + (size_t)o * I_DIM;
    int kd[4] = {kd4.x, kd4.y, kd4.z, kd4.w};
    float v[4];
#pragma unroll
    for (int e = 0; e < 4; e++) {
        int g = kd[e] >> 2;
        int p = kd[e] & 3;
        int2 md = *reinterpret_cast<const int2*>(md_row + 2 * g);
        float r = 0.0f;
        if (md.x == p)      r = __ldg(w_row + 2 * g);
        else if (md.y == p) r = __ldg(w_row + 2 * g + 1);
        v[e] = r;
    }
    __half2 h01 = __floats2half2_rn(v[0], v[1]);
    __half2 h23 = __floats2half2_rn(v[2], v[3]);
    uint2 pack;
    pack.x = *reinterpret_cast<uint32_t*>(&h01);
    pack.y = *reinterpret_cast<uint32_t*>(&h23);
    *reinterpret_cast<uint2*>(g_Wh + (size_t)o * K_ACT + j0) = pack;
}

// ===========================================================================
// Kernel 2: fp16-convert activations (8 floats -> 8 halves per thread)
// ===========================================================================
__global__ void convert_b_kernel(const float4* __restrict__ input) {
    int t = blockIdx.x * blockDim.x + threadIdx.x;
    float4 f0 = input[t * 2];
    float4 f1 = input[t * 2 + 1];
    __half2 h[4];
    h[0] = __floats2half2_rn(f0.x, f0.y);
    h[1] = __floats2half2_rn(f0.z, f0.w);
    h[2] = __floats2half2_rn(f1.x, f1.y);
    h[3] = __floats2half2_rn(f1.z, f1.w);
    *(reinterpret_cast<uint4*>(g_Bh) + t) = *reinterpret_cast<uint4*>(h);
}

// ===========================================================================
// Kernel 3: zero only INACTIVE output rows (active rows rewritten by GEMM).
//   indices is sorted -> binary search membership per row.
// ===========================================================================
__global__ void zero_inactive_kernel(float4* __restrict__ out,
                                     const int* __restrict__ indices) {
    int row = blockIdx.x;
    int lo = 0, hi = O_DIM;
    while (lo < hi) {
        int mid = (lo + hi) >> 1;
        if (__ldg(indices + mid) < row) lo = mid + 1; else hi = mid;
    }
    if (lo < O_DIM && __ldg(indices + lo) == row) return;   // active: skip
    float4 z = make_float4(0.f, 0.f, 0.f, 0.f);
    float4* p = out + (size_t)row * (N_TOK / 4);
#pragma unroll
    for (int i = 0; i < N_TOK / 4 / 256; i++)
        p[i * 256 + threadIdx.x] = z;
}

// ===========================================================================
// Kernel 4: fp16 mma.sync m16n8k16 GEMM with row-scatter epilogue
//   CTA 128x128, KC=64 halves, 256 thr = 8 warps (4m x 2n), warp tile 32x64.
//   3-stage cp.async circular buffer, ONE __syncthreads per K-chunk.
// ===========================================================================
#define MT      128
#define NT      128
#define KC      64
#define KITERS  (K_ACT / KC)          // 32
#define STAGES  3
#define STRH    72                    // halves per smem row (144 B)
#define ROWB    (STRH * 2)            // 144 bytes
#define A_BYTES (MT * ROWB)           // 18432
#define B_BYTES (NT * ROWB)           // 18432
#define STG_BYTES (A_BYTES + B_BYTES) // 36864
#define SMEM_DYN (STAGES * STG_BYTES) // 110592 B -> 2 CTAs/SM (216 KB)

__device__ __forceinline__ uint32_t smem_u32(const void* p) {
    uint32_t a;
    asm("{ .reg .u64 t; cvta.to.shared.u64 t, %1; cvt.u32.u64 %0, t; }"
        : "=r"(a) : "l"(p));
    return a;
}
__device__ __forceinline__ void ldsm_x4(uint32_t* r, uint32_t addr) {
    asm volatile("ldmatrix.sync.aligned.m8n8.x4.shared.b16 {%0,%1,%2,%3}, [%4];"
                 : "=r"(r[0]), "=r"(r[1]), "=r"(r[2]), "=r"(r[3]) : "r"(addr));
}
__device__ __forceinline__ void mma_f16(float* c, const uint32_t* a,
                                        uint32_t b0, uint32_t b1) {
    asm volatile(
        "mma.sync.aligned.m16n8k16.row.col.f32.f16.f16.f32 "
        "{%0,%1,%2,%3}, {%4,%5,%6,%7}, {%8,%9}, {%0,%1,%2,%3};"
        : "+f"(c[0]), "+f"(c[1]), "+f"(c[2]), "+f"(c[3])
        : "r"(a[0]), "r"(a[1]), "r"(a[2]), "r"(a[3]), "r"(b0), "r"(b1));
}
__device__ __forceinline__ void cp_async16(void* dst_smem, const void* src) {
    uint32_t d;
    asm("{ .reg .u64 t; cvta.to.shared.u64 t, %1; cvt.u32.u64 %0, t; }"
        : "=r"(d) : "l"(dst_smem));
    asm volatile("cp.async.cg.shared.global [%0], [%1], 16;" :: "r"(d), "l"(src));
}

__global__ __launch_bounds__(256, 2)
void gemm_mma_kernel(const int* __restrict__ indices,
                     float*     __restrict__ out) {
    extern __shared__ char smem[];
    const __half* Ag = g_Wh;
    const __half* Bg = g_Bh;

    const int tid  = threadIdx.x;
    const int lane = tid & 31;
    const int wid  = tid >> 5;
    const int wm   = wid >> 1;        // 0..3 -> m offset wm*32
    const int wn   = wid & 1;         // 0..1 -> n offset wn*64
    const int bm   = blockIdx.y * MT;
    const int bn   = blockIdx.x * NT;

    float acc[2][8][4];
#pragma unroll
    for (int mi = 0; mi < 2; mi++)
#pragma unroll
        for (int ni = 0; ni < 8; ni++)
#pragma unroll
            for (int q = 0; q < 4; q++) acc[mi][ni][q] = 0.0f;

    // cp.async stage loader: A 128x64h, B 128x64h; 8 halves (16B) per op
    auto load_stage = [&](int kc, int s) {
        char* As = smem + s * STG_BYTES;
        char* Bs = As + A_BYTES;
#pragma unroll
        for (int i = 0; i < 4; i++) {               // A: 1024 ops
            int f = i * 256 + tid;
            int row = f >> 3, c = (f & 7) << 3;     // halves
            cp_async16(As + row * ROWB + c * 2,
                       Ag + (size_t)(bm + row) * K_ACT + kc * KC + c);
        }
#pragma unroll
        for (int i = 0; i < 4; i++) {               // B: 1024 ops
            int f = i * 256 + tid;
            int row = f >> 3, c = (f & 7) << 3;
            cp_async16(Bs + row * ROWB + c * 2,
                       Bg + (size_t)(bn + row) * K_ACT + kc * KC + c);
        }
    };

    // ldmatrix per-lane row addressing (byte offsets)
    const uint32_t smem_b = smem_u32(smem);
    const int a_row  = wm * 32 + (lane & 7) + (lane & 8);
    const int a_koff = (lane >> 4) << 3;            // halves
    const int b_row  = wn * 64 + (lane & 7) + ((lane >> 4) << 3);
    const int b_koff = (lane & 8);                  // halves

    // prologue: stages 0 and 1 in flight
    load_stage(0, 0);
    asm volatile("cp.async.commit_group;" ::: "memory");
    load_stage(1, 1);
    asm volatile("cp.async.commit_group;" ::: "memory");

    int s_cur = 0, s_nxt = 2;
    for (int kc = 0; kc < KITERS; kc++) {
        asm volatile("cp.async.wait_group 1;" ::: "memory");   // stage kc ready
        __syncthreads();   // all warps done with compute(kc-1) -> slot s_nxt free

        if (kc + 2 < KITERS) load_stage(kc + 2, s_nxt);
        asm volatile("cp.async.commit_group;" ::: "memory");

        const uint32_t As = smem_b + s_cur * STG_BYTES;
        const uint32_t Bs = As + A_BYTES;
        const uint32_t aAddr = As + a_row * ROWB + a_koff * 2;
        const uint32_t bAddr = Bs + b_row * ROWB + b_koff * 2;

#pragma unroll
        for (int ks = 0; ks < 4; ks++) {
            const int k0b = ks * 32;                // k16 * 2 bytes
            uint32_t aa[2][4];
#pragma unroll
            for (int mi = 0; mi < 2; mi++)
                ldsm_x4(aa[mi], aAddr + mi * 16 * ROWB + k0b);
            uint32_t bb[4][4];
#pragma unroll
            for (int pr = 0; pr < 4; pr++)
                ldsm_x4(bb[pr], bAddr + pr * 16 * ROWB + k0b);
#pragma unroll
            for (int mi = 0; mi < 2; mi++)
#pragma unroll
                for (int ni = 0; ni < 8; ni++)
                    mma_f16(acc[mi][ni], aa[mi],
                            bb[ni >> 1][(ni & 1) * 2],
                            bb[ni >> 1][(ni & 1) * 2 + 1]);
        }
        s_cur = (s_cur + 1 == STAGES) ? 0 : s_cur + 1;
        s_nxt = (s_nxt + 1 == STAGES) ? 0 : s_nxt + 1;
    }

    // ---- epilogue: scatter rows via indices ----
#pragma unroll
    for (int mi = 0; mi < 2; mi++) {
        int r0 = bm + wm * 32 + mi * 16 + (lane >> 2);
        int o0 = __ldg(indices + r0);
        int o1 = __ldg(indices + r0 + 8);
        float* d0 = out + (size_t)o0 * N_TOK + bn + wn * 64 + 2 * (lane & 3);
        float* d1 = out + (size_t)o1 * N_TOK + bn + wn * 64 + 2 * (lane & 3);
#pragma unroll
        for (int ni = 0; ni < 8; ni++) {
            float2 v0 = make_float2(acc[mi][ni][0], acc[mi][ni][1]);
            float2 v1 = make_float2(acc[mi][ni][2], acc[mi][ni][3]);
            *reinterpret_cast<float2*>(d0 + ni * 8) = v0;
            *reinterpret_cast<float2*>(d1 + ni * 8) = v1;
        }
    }
}

// ===========================================================================
// Host launcher
// ===========================================================================
extern "C" void kernel_launch(void* const* d_in, const int* in_sizes, int n_in,
                              void* d_out, int out_size) {
    const float* input    = (const float*)d_in[0];
    const int*   idx      = (const int*)  d_in[1];
    const float* weight   = (const float*)d_in[2];
    const int*   indices  = (const int*)  d_in[3];
    const int*   metadata = (const int*)  d_in[4];
    if (in_sizes[1] == O_DIM && in_sizes[3] == K_ACT) {
        const int* t = idx; idx = indices; indices = t;
    }
    float* out = (float*)d_out;

    cudaFuncSetAttribute(gemm_mma_kernel,
                         cudaFuncAttributeMaxDynamicSharedMemorySize, SMEM_DYN);

    // 1) gather + fp16-convert weight (4 elems/thread)
    build_wg_kernel<<<(O_DIM * K_ACT / 4) / 256, 256>>>(weight, idx, metadata);
    // 2) fp16-convert activations
    convert_b_kernel<<<(N_TOK * K_ACT / 8) / 256, 256>>>((const float4*)input);
    // 3) zero only inactive output rows
    zero_inactive_kernel<<<M_DENSE, 256>>>((float4*)out, indices);
    // 4) tensor-core GEMM + scatter
    dim3 grid(N_TOK / NT, O_DIM / MT);   // 32 x 32
    gemm_mma_kernel<<<grid, 256, SMEM_DYN>>>(indices, out);
}